// round 8
// baseline (speedup 1.0000x reference)
#include <cuda_runtime.h>
#include <cuda_fp16.h>
#include <math.h>
#include <stdint.h>

using u32 = unsigned int;

constexpr int Cc = 256, Vk = 64, NBS = 2048, NN = 16384;
constexpr int BP = 2;                       // batches per pipeline pair
constexpr int ROWS_PER_BP = BP * 256;       // 512 ctx rows per pair

// Scratch (device globals; allocation-free)
__device__ __half g_ch[NBS * Cc], g_cl[NBS * Cc];                   // ctx split
__device__ __half g_Wh[(size_t)NN * Cc], g_Wl[(size_t)NN * Cc];     // W2' [n'=(k,j)][i]
// tmp for ONE batch-pair only (reused; stays L2-resident): [local_bs][k][j]
__device__ __half g_th[(size_t)ROWS_PER_BP * Vk * Cc];              // 16.8 MB
__device__ __half g_tl[(size_t)ROWS_PER_BP * Vk * Cc];              // 16.8 MB
__device__ float g_Arow[NBS * Vk], g_Beta[NBS * Vk];

// ---------------- helpers ----------------
__device__ __forceinline__ u32 smem_u32(const void* p) {
    u32 a;
    asm("{ .reg .u64 t; cvta.to.shared.u64 t, %1; cvt.u32.u64 %0, t; }" : "=r"(a) : "l"(p));
    return a;
}
#define SWZ(o) ((o) ^ (((o) >> 3) & 0x70))

__device__ __forceinline__ void cpa16(u32 dst, const void* src) {
    asm volatile("cp.async.cg.shared.global [%0], [%1], 16;" :: "r"(dst), "l"(src));
}
#define CP_COMMIT() asm volatile("cp.async.commit_group;")
#define CP_WAIT0()  asm volatile("cp.async.wait_group 0;")

__device__ __forceinline__ void ldmA(u32 addr, u32& a0, u32& a1, u32& a2, u32& a3) {
    asm volatile("ldmatrix.sync.aligned.m8n8.x4.shared.b16 {%0,%1,%2,%3}, [%4];"
                 : "=r"(a0), "=r"(a1), "=r"(a2), "=r"(a3) : "r"(addr));
}
__device__ __forceinline__ void ldmB(u32 addr, u32& b0, u32& b1) {
    asm volatile("ldmatrix.sync.aligned.m8n8.x2.shared.b16 {%0,%1}, [%2];"
                 : "=r"(b0), "=r"(b1) : "r"(addr));
}
__device__ __forceinline__ void mma16816(float* c, const u32* a, const u32* b) {
    asm volatile("mma.sync.aligned.m16n8k16.row.col.f32.f16.f16.f32 "
                 "{%0,%1,%2,%3}, {%4,%5,%6,%7}, {%8,%9}, {%0,%1,%2,%3};"
                 : "+f"(c[0]), "+f"(c[1]), "+f"(c[2]), "+f"(c[3])
                 : "r"(a[0]), "r"(a[1]), "r"(a[2]), "r"(a[3]), "r"(b[0]), "r"(b[1]));
}

// ---------------- prep kernels ----------------
__global__ void k_split_ctx(const float* __restrict__ ctx) {
    int i = blockIdx.x * 256 + threadIdx.x;
    float x = ctx[i];
    __half h = __float2half_rn(x);
    g_ch[i] = h;
    g_cl[i] = __float2half_rn(x - __half2float(h));
}

// W2'[(k*256+j)][i] = W[i][j*64+k] + (i==j)*lmw[k*256+j], split hi/lo
__global__ void k_prep_w(const float* __restrict__ W, const float* __restrict__ lmw) {
    __shared__ float tile[32][33];
    int tx = threadIdx.x, ty = threadIdx.y;          // (32, 8)
    int n0 = blockIdx.x * 32, i0 = blockIdx.y * 32;
    #pragma unroll
    for (int q = 0; q < 4; ++q) {
        int i = i0 + ty + q * 8, n = n0 + tx;
        float v = W[(size_t)i * NN + n];
        int j = n >> 6, k = n & 63;
        if (i == j) v += lmw[k * Cc + j];
        tile[ty + q * 8][tx] = v;
    }
    __syncthreads();
    #pragma unroll
    for (int q = 0; q < 4; ++q) {
        int n = n0 + ty + q * 8, i = i0 + tx;
        float v = tile[tx][ty + q * 8];
        int j = n >> 6, k = n & 63;
        size_t np = (size_t)(k * 256 + j) * Cc + i;
        __half h = __float2half_rn(v);
        g_Wh[np] = h;
        g_Wl[np] = __float2half_rn(v - __half2float(h));
    }
}

__global__ void k_rowcol(const float* __restrict__ ctx,
                         const float* __restrict__ l1w, const float* __restrict__ l1b,
                         const float* __restrict__ l2w, const float* __restrict__ l2b,
                         const float* __restrict__ lmb,
                         const float* __restrict__ ldw, const float* __restrict__ ldb,
                         const float* __restrict__ bias) {
    __shared__ float xs[Cc];
    int r = blockIdx.x, t = threadIdx.x;
    for (int c = t; c < Cc; c += 128) xs[c] = ctx[r * Cc + c];
    __syncthreads();
    if (t < 64) {
        int k = t; float acc = 0.f;
        #pragma unroll 8
        for (int c = 0; c < Cc; ++c) acc = fmaf(xs[c], l1w[k * Cc + c] + ldw[k * Cc + c], acc);
        g_Arow[r * Vk + k] = acc + l1b[k];
    } else {
        int k = t - 64; float acc = 0.f;
        #pragma unroll 8
        for (int c = 0; c < Cc; ++c) acc = fmaf(xs[c], l2w[k * Cc + c] - ldw[k * Cc + c], acc);
        g_Beta[r * Vk + k] = acc + l2b[k] + lmb[k] + ldb[k] + bias[k];
    }
}

// ---------------- stage 1 (per batch-pair bp): tmp = ctx_rows @ W2' ---------
// grid (128 n'-tiles, 4 m-tiles), 256 thr. CTA 128x128, BK=64, 4 chunks.
__global__ __launch_bounds__(256) void k_mma1(int bp) {
    extern __shared__ char sm[];
    const u32 smb = smem_u32(sm);
    const int tid = threadIdx.x, lane = tid & 31, wid = tid >> 5;
    const int wm = wid >> 2, wn = wid & 3;           // 2 x 4 warps; warp tile 64x32
    const int rowBase = blockIdx.y * 128;            // local row 0..511
    const int colBase = blockIdx.x * 128;
    const size_t gRow = (size_t)bp * ROWS_PER_BP + rowBase;

    auto load = [&](int c, int p) {
        u32 d = smb + p * 65536;
        const char* sA_h = (const char*)g_ch + (gRow * Cc + c * 64) * 2;
        const char* sA_l = (const char*)g_cl + (gRow * Cc + c * 64) * 2;
        const char* sB_h = (const char*)g_Wh + ((size_t)colBase * Cc + c * 64) * 2;
        const char* sB_l = (const char*)g_Wl + ((size_t)colBase * Cc + c * 64) * 2;
        #pragma unroll
        for (int q = 0; q < 4; ++q) {
            int s = tid + q * 256;
            int r = s >> 3, co = (s & 7) * 16;
            u32 sw = SWZ(r * 128 + co);
            cpa16(d + sw,         sA_h + (size_t)r * 512 + co);
            cpa16(d + 16384 + sw, sA_l + (size_t)r * 512 + co);
            cpa16(d + 32768 + sw, sB_h + (size_t)r * 512 + co);
            cpa16(d + 49152 + sw, sB_l + (size_t)r * 512 + co);
        }
    };

    float acc[4][4][4];
    #pragma unroll
    for (int t = 0; t < 4; ++t)
        #pragma unroll
        for (int u = 0; u < 4; ++u)
            #pragma unroll
            for (int e = 0; e < 4; ++e) acc[t][u][e] = 0.f;

    load(0, 0); CP_COMMIT();

    for (int c = 0; c < 4; ++c) {
        CP_WAIT0();
        __syncthreads();
        if (c < 3) { load(c + 1, (c + 1) & 1); CP_COMMIT(); }
        u32 bufA = smb + (c & 1) * 65536;
        u32 bufB = bufA + 32768;
        #pragma unroll
        for (int ks = 0; ks < 4; ++ks) {
            u32 ah[4][4], al[4][4], bh[4][2], bl[4][2];
            int arow = wm * 64 + (lane & 15);
            int acol = ks * 32 + (lane >> 4) * 16;
            #pragma unroll
            for (int t = 0; t < 4; ++t) {
                u32 sw = SWZ((arow + t * 16) * 128 + acol);
                ldmA(bufA + sw,         ah[t][0], ah[t][1], ah[t][2], ah[t][3]);
                ldmA(bufA + 16384 + sw, al[t][0], al[t][1], al[t][2], al[t][3]);
            }
            int brow = wn * 32 + (lane & 7);
            int bcol = ks * 32 + ((lane >> 3) & 1) * 16;
            #pragma unroll
            for (int u = 0; u < 4; ++u) {
                u32 sw = SWZ((brow + u * 8) * 128 + bcol);
                ldmB(bufB + sw,         bh[u][0], bh[u][1]);
                ldmB(bufB + 16384 + sw, bl[u][0], bl[u][1]);
            }
            #pragma unroll
            for (int t = 0; t < 4; ++t)
                #pragma unroll
                for (int u = 0; u < 4; ++u) {
                    mma16816(acc[t][u], ah[t], bh[u]);
                    mma16816(acc[t][u], ah[t], bl[u]);
                    mma16816(acc[t][u], al[t], bh[u]);
                }
        }
        __syncthreads();
    }

    // ---- staged epilogue -> coalesced stores into local tmp
    __half* sh = (__half*)sm;
    __half* sl = (__half*)(sm + 34816);
    #pragma unroll
    for (int t = 0; t < 4; ++t)
        #pragma unroll
        for (int u = 0; u < 4; ++u) {
            int jl = wn * 32 + u * 8 + (lane & 3) * 2;
            #pragma unroll
            for (int h = 0; h < 2; ++h) {
                int ml = wm * 64 + t * 16 + (lane >> 2) + h * 8;
                float v0 = acc[t][u][h * 2], v1 = acc[t][u][h * 2 + 1];
                __half h0 = __float2half_rn(v0), h1 = __float2half_rn(v1);
                __half2 hv; hv.x = h0; hv.y = h1;
                __half2 lv;
                lv.x = __float2half_rn(v0 - __half2float(h0));
                lv.y = __float2half_rn(v1 - __half2float(h1));
                *(__half2*)&sh[ml * 136 + jl] = hv;
                *(__half2*)&sl[ml * 136 + jl] = lv;
            }
        }
    __syncthreads();

    const int k = colBase >> 8;                 // n' = k*256 + j
    const int jb = (colBase & 255);             // 0 or 128
    #pragma unroll
    for (int it = 0; it < 8; ++it) {
        int lin = it * 256 + tid;
        int m = lin >> 4;
        int jo = (lin & 15) * 8;
        uint4 vh = *(const uint4*)&sh[m * 136 + jo];
        uint4 vl = *(const uint4*)&sl[m * 136 + jo];
        size_t off = ((size_t)(rowBase + m) * 64 + k) * 256 + jb + jo;   // LOCAL row
        *(uint4*)(g_th + off) = vh;
        *(uint4*)(g_tl + off) = vl;
    }
}

// ---------------- stage 2 (per bp): out = tanh(ctx_b @ tmp^T + Arow + Beta) -
// grid (128 s-pairs, 2 ztile, 2 b_local), 256 thr. CTA 128(z) x 128(n).
__global__ __launch_bounds__(256) void k_mma2(int bp, float* __restrict__ out) {
    extern __shared__ char sm[];
    __shared__ float beta_sm[128];
    const u32 smb = smem_u32(sm);
    const int tid = threadIdx.x, lane = tid & 31, wid = tid >> 5;
    const int wm = wid >> 2, wn = wid & 3;
    const int s0 = blockIdx.x * 2, zBase = blockIdx.y * 128;
    const int b_loc = blockIdx.z;
    const int b_glob = bp * BP + b_loc;
    const int bs0_glob = b_glob * 256 + s0;
    const size_t bRowLoc = (size_t)(b_loc * 256 + s0) * 64;     // local tmp row

    if (tid < 128) beta_sm[tid] = g_Beta[(size_t)bs0_glob * Vk + tid];

    auto load = [&](int c, int p) {
        u32 d = smb + p * 65536;
        const char* sA_h = (const char*)g_ch + (((size_t)(b_glob * 256 + zBase)) * Cc + c * 64) * 2;
        const char* sA_l = (const char*)g_cl + (((size_t)(b_glob * 256 + zBase)) * Cc + c * 64) * 2;
        const char* sB_h = (const char*)g_th + (bRowLoc * Cc + c * 64) * 2;
        const char* sB_l = (const char*)g_tl + (bRowLoc * Cc + c * 64) * 2;
        #pragma unroll
        for (int q = 0; q < 4; ++q) {
            int s = tid + q * 256;
            int r = s >> 3, co = (s & 7) * 16;
            u32 sw = SWZ(r * 128 + co);
            cpa16(d + sw,         sA_h + (size_t)r * 512 + co);
            cpa16(d + 16384 + sw, sA_l + (size_t)r * 512 + co);
            cpa16(d + 32768 + sw, sB_h + (size_t)r * 512 + co);
            cpa16(d + 49152 + sw, sB_l + (size_t)r * 512 + co);
        }
    };

    float acc[4][4][4];
    #pragma unroll
    for (int t = 0; t < 4; ++t)
        #pragma unroll
        for (int u = 0; u < 4; ++u)
            #pragma unroll
            for (int e = 0; e < 4; ++e) acc[t][u][e] = 0.f;

    load(0, 0); CP_COMMIT();

    for (int c = 0; c < 4; ++c) {
        CP_WAIT0();
        __syncthreads();
        if (c < 3) { load(c + 1, (c + 1) & 1); CP_COMMIT(); }
        u32 bufA = smb + (c & 1) * 65536;
        u32 bufB = bufA + 32768;
        #pragma unroll
        for (int ks = 0; ks < 4; ++ks) {
            u32 ah[4][4], al[4][4], bh[4][2], bl[4][2];
            int arow = wm * 64 + (lane & 15);
            int acol = ks * 32 + (lane >> 4) * 16;
            #pragma unroll
            for (int t = 0; t < 4; ++t) {
                u32 sw = SWZ((arow + t * 16) * 128 + acol);
                ldmA(bufA + sw,         ah[t][0], ah[t][1], ah[t][2], ah[t][3]);
                ldmA(bufA + 16384 + sw, al[t][0], al[t][1], al[t][2], al[t][3]);
            }
            int brow = wn * 32 + (lane & 7);
            int bcol = ks * 32 + ((lane >> 3) & 1) * 16;
            #pragma unroll
            for (int u = 0; u < 4; ++u) {
                u32 sw = SWZ((brow + u * 8) * 128 + bcol);
                ldmB(bufB + sw,         bh[u][0], bh[u][1]);
                ldmB(bufB + 16384 + sw, bl[u][0], bl[u][1]);
            }
            #pragma unroll
            for (int t = 0; t < 4; ++t)
                #pragma unroll
                for (int u = 0; u < 4; ++u) {
                    mma16816(acc[t][u], ah[t], bh[u]);
                    mma16816(acc[t][u], ah[t], bl[u]);
                    mma16816(acc[t][u], al[t], bh[u]);
                }
        }
        __syncthreads();
    }

    // ---- staged epilogue: finish math, stage fp32 tile, coalesced stores
    float* so = (float*)sm;
    #pragma unroll
    for (int t = 0; t < 4; ++t)
        #pragma unroll
        for (int u = 0; u < 4; ++u) {
            int n = wn * 32 + u * 8 + (lane & 3) * 2;
            int k0 = n & 63;
            #pragma unroll
            for (int h = 0; h < 2; ++h) {
                int zl = wm * 64 + t * 16 + (lane >> 2) + h * 8;
                float2 ar = *(const float2*)&g_Arow[(size_t)(b_glob * 256 + zBase + zl) * Vk + k0];
                float2 o;
                o.x = tanhf(acc[t][u][h * 2]     + ar.x + beta_sm[n]);
                o.y = tanhf(acc[t][u][h * 2 + 1] + ar.y + beta_sm[n + 1]);
                *(float2*)&so[zl * 132 + n] = o;
            }
        }
    __syncthreads();

    #pragma unroll
    for (int it = 0; it < 16; ++it) {
        int lin = it * 256 + tid;
        int k4 = (lin & 15) * 4;
        int z  = (lin >> 4) & 127;
        int s_local = lin >> 11;
        float4 v = *(const float4*)&so[z * 132 + s_local * 64 + k4];
        size_t oOff = (((size_t)(bs0_glob + s_local) * 256 + zBase + z) * Vk) + k4;
        *(float4*)&out[oOff] = v;
    }
}

// ---------------------------------------------------------------------------
extern "C" void kernel_launch(void* const* d_in, const int* in_sizes, int n_in,
                              void* d_out, int out_size) {
    const float* ctx       = (const float*)d_in[0];
    const float* W         = (const float*)d_in[1];
    const float* bias      = (const float*)d_in[2];
    const float* lin1_w    = (const float*)d_in[3];
    const float* lin1_b    = (const float*)d_in[4];
    const float* lin2_w    = (const float*)d_in[5];
    const float* lin2_b    = (const float*)d_in[6];
    const float* linmul_w  = (const float*)d_in[7];
    const float* linmul_b  = (const float*)d_in[8];
    const float* lindiff_w = (const float*)d_in[9];
    const float* lindiff_b = (const float*)d_in[10];
    float* out = (float*)d_out;

    static bool attr_set = false;
    if (!attr_set) {
        cudaFuncSetAttribute(k_mma1, cudaFuncAttributeMaxDynamicSharedMemorySize, 131072);
        cudaFuncSetAttribute(k_mma2, cudaFuncAttributeMaxDynamicSharedMemorySize, 131072);
        attr_set = true;
    }

    k_split_ctx<<<NBS * Cc / 256, 256>>>(ctx);
    k_prep_w<<<dim3(NN / 32, Cc / 32), dim3(32, 8)>>>(W, linmul_w);
    k_rowcol<<<NBS, 128>>>(ctx, lin1_w, lin1_b, lin2_w, lin2_b,
                           linmul_b, lindiff_w, lindiff_b, bias);

    for (int bp = 0; bp < 8 / BP; ++bp) {
        k_mma1<<<dim3(128, ROWS_PER_BP / 128), 256, 131072>>>(bp);
        k_mma2<<<dim3(128, 2, BP), 256, 131072>>>(bp, out);
    }
}

// round 9
// speedup vs baseline: 1.0657x; 1.0657x over previous
#include <cuda_runtime.h>
#include <cuda_fp16.h>
#include <math.h>
#include <stdint.h>

using u32 = unsigned int;

constexpr int Cc = 256, Vk = 64, NBS = 2048, NN = 16384;

// Scratch (device globals; allocation-free)
__device__ __half g_ch[NBS * Cc], g_cl[NBS * Cc];                   // ctx split
__device__ __half g_Wh[(size_t)NN * Cc], g_Wl[(size_t)NN * Cc];     // W2' [n'=(k,j)][i]
__device__ __half g_th[(size_t)NBS * Vk * Cc];                      // tmp hi [bs][k][j]
__device__ __half g_tl[(size_t)NBS * Vk * Cc];                      // tmp lo
__device__ float g_Arow[NBS * Vk], g_Beta[NBS * Vk];

// ---------------- helpers ----------------
__device__ __forceinline__ u32 smem_u32(const void* p) {
    u32 a;
    asm("{ .reg .u64 t; cvta.to.shared.u64 t, %1; cvt.u32.u64 %0, t; }" : "=r"(a) : "l"(p));
    return a;
}
#define SWZ(o) ((o) ^ (((o) >> 3) & 0x70))

__device__ __forceinline__ void cpa16(u32 dst, const void* src) {
    asm volatile("cp.async.cg.shared.global [%0], [%1], 16;" :: "r"(dst), "l"(src));
}
#define CP_COMMIT() asm volatile("cp.async.commit_group;")
#define CP_WAIT0()  asm volatile("cp.async.wait_group 0;")

__device__ __forceinline__ void ldmA(u32 addr, u32& a0, u32& a1, u32& a2, u32& a3) {
    asm volatile("ldmatrix.sync.aligned.m8n8.x4.shared.b16 {%0,%1,%2,%3}, [%4];"
                 : "=r"(a0), "=r"(a1), "=r"(a2), "=r"(a3) : "r"(addr));
}
__device__ __forceinline__ void ldmB(u32 addr, u32& b0, u32& b1) {
    asm volatile("ldmatrix.sync.aligned.m8n8.x2.shared.b16 {%0,%1}, [%2];"
                 : "=r"(b0), "=r"(b1) : "r"(addr));
}
__device__ __forceinline__ void mma16816(float* c, const u32* a, const u32* b) {
    asm volatile("mma.sync.aligned.m16n8k16.row.col.f32.f16.f16.f32 "
                 "{%0,%1,%2,%3}, {%4,%5,%6,%7}, {%8,%9}, {%0,%1,%2,%3};"
                 : "+f"(c[0]), "+f"(c[1]), "+f"(c[2]), "+f"(c[3])
                 : "r"(a[0]), "r"(a[1]), "r"(a[2]), "r"(a[3]), "r"(b[0]), "r"(b[1]));
}
// single-MUFU tanh (handles saturation internally; abs err ~1e-4)
__device__ __forceinline__ float ftanh(float x) {
    float y;
    asm("tanh.approx.f32 %0, %1;" : "=f"(y) : "f"(x));
    return y;
}

// ---------------- prep kernels ----------------
__global__ void k_split_ctx(const float* __restrict__ ctx) {
    int i = blockIdx.x * 256 + threadIdx.x;
    float x = ctx[i];
    __half h = __float2half_rn(x);
    g_ch[i] = h;
    g_cl[i] = __float2half_rn(x - __half2float(h));
}

// W2'[(k*256+j)][i] = W[i][j*64+k] + (i==j)*lmw[k*256+j], split hi/lo
__global__ void k_prep_w(const float* __restrict__ W, const float* __restrict__ lmw) {
    __shared__ float tile[32][33];
    int tx = threadIdx.x, ty = threadIdx.y;          // (32, 8)
    int n0 = blockIdx.x * 32, i0 = blockIdx.y * 32;
    #pragma unroll
    for (int q = 0; q < 4; ++q) {
        int i = i0 + ty + q * 8, n = n0 + tx;
        float v = W[(size_t)i * NN + n];
        int j = n >> 6, k = n & 63;
        if (i == j) v += lmw[k * Cc + j];
        tile[ty + q * 8][tx] = v;
    }
    __syncthreads();
    #pragma unroll
    for (int q = 0; q < 4; ++q) {
        int n = n0 + ty + q * 8, i = i0 + tx;
        float v = tile[tx][ty + q * 8];
        int j = n >> 6, k = n & 63;
        size_t np = (size_t)(k * 256 + j) * Cc + i;
        __half h = __float2half_rn(v);
        g_Wh[np] = h;
        g_Wl[np] = __float2half_rn(v - __half2float(h));
    }
}

__global__ void k_rowcol(const float* __restrict__ ctx,
                         const float* __restrict__ l1w, const float* __restrict__ l1b,
                         const float* __restrict__ l2w, const float* __restrict__ l2b,
                         const float* __restrict__ lmb,
                         const float* __restrict__ ldw, const float* __restrict__ ldb,
                         const float* __restrict__ bias) {
    __shared__ float xs[Cc];
    int r = blockIdx.x, t = threadIdx.x;
    for (int c = t; c < Cc; c += 128) xs[c] = ctx[r * Cc + c];
    __syncthreads();
    if (t < 64) {
        int k = t; float acc = 0.f;
        #pragma unroll 8
        for (int c = 0; c < Cc; ++c) acc = fmaf(xs[c], l1w[k * Cc + c] + ldw[k * Cc + c], acc);
        g_Arow[r * Vk + k] = acc + l1b[k];
    } else {
        int k = t - 64; float acc = 0.f;
        #pragma unroll 8
        for (int c = 0; c < Cc; ++c) acc = fmaf(xs[c], l2w[k * Cc + c] - ldw[k * Cc + c], acc);
        g_Beta[r * Vk + k] = acc + l2b[k] + lmb[k] + ldb[k] + bias[k];
    }
}

// ---------------- stage 1: tmp = ctx @ W2' (HMMA fp16 split) ----------------
// grid (128 n'-tiles, 16 m-tiles), 256 thr. CTA 128x128, BK=64, 4 chunks.
__global__ __launch_bounds__(256) void k_mma1() {
    extern __shared__ char sm[];
    const u32 smb = smem_u32(sm);
    const int tid = threadIdx.x, lane = tid & 31, wid = tid >> 5;
    const int wm = wid >> 2, wn = wid & 3;           // 2 x 4 warps; warp tile 64x32
    const int rowBase = blockIdx.y * 128;
    const int colBase = blockIdx.x * 128;

    auto load = [&](int c, int p) {
        u32 d = smb + p * 65536;
        const char* sA_h = (const char*)g_ch + ((size_t)rowBase * Cc + c * 64) * 2;
        const char* sA_l = (const char*)g_cl + ((size_t)rowBase * Cc + c * 64) * 2;
        const char* sB_h = (const char*)g_Wh + ((size_t)colBase * Cc + c * 64) * 2;
        const char* sB_l = (const char*)g_Wl + ((size_t)colBase * Cc + c * 64) * 2;
        #pragma unroll
        for (int q = 0; q < 4; ++q) {
            int s = tid + q * 256;
            int r = s >> 3, co = (s & 7) * 16;
            u32 sw = SWZ(r * 128 + co);
            cpa16(d + sw,         sA_h + (size_t)r * 512 + co);
            cpa16(d + 16384 + sw, sA_l + (size_t)r * 512 + co);
            cpa16(d + 32768 + sw, sB_h + (size_t)r * 512 + co);
            cpa16(d + 49152 + sw, sB_l + (size_t)r * 512 + co);
        }
    };

    float acc[4][4][4];
    #pragma unroll
    for (int t = 0; t < 4; ++t)
        #pragma unroll
        for (int u = 0; u < 4; ++u)
            #pragma unroll
            for (int e = 0; e < 4; ++e) acc[t][u][e] = 0.f;

    load(0, 0); CP_COMMIT();

    for (int c = 0; c < 4; ++c) {
        CP_WAIT0();
        __syncthreads();
        if (c < 3) { load(c + 1, (c + 1) & 1); CP_COMMIT(); }
        u32 bufA = smb + (c & 1) * 65536;
        u32 bufB = bufA + 32768;
        #pragma unroll
        for (int ks = 0; ks < 4; ++ks) {
            u32 ah[4][4], al[4][4], bh[4][2], bl[4][2];
            int arow = wm * 64 + (lane & 15);
            int acol = ks * 32 + (lane >> 4) * 16;
            #pragma unroll
            for (int t = 0; t < 4; ++t) {
                u32 sw = SWZ((arow + t * 16) * 128 + acol);
                ldmA(bufA + sw,         ah[t][0], ah[t][1], ah[t][2], ah[t][3]);
                ldmA(bufA + 16384 + sw, al[t][0], al[t][1], al[t][2], al[t][3]);
            }
            int brow = wn * 32 + (lane & 7);
            int bcol = ks * 32 + ((lane >> 3) & 1) * 16;
            #pragma unroll
            for (int u = 0; u < 4; ++u) {
                u32 sw = SWZ((brow + u * 8) * 128 + bcol);
                ldmB(bufB + sw,         bh[u][0], bh[u][1]);
                ldmB(bufB + 16384 + sw, bl[u][0], bl[u][1]);
            }
            #pragma unroll
            for (int t = 0; t < 4; ++t)
                #pragma unroll
                for (int u = 0; u < 4; ++u) {
                    mma16816(acc[t][u], ah[t], bh[u]);
                    mma16816(acc[t][u], ah[t], bl[u]);
                    mma16816(acc[t][u], al[t], bh[u]);
                }
        }
        __syncthreads();
    }

    // ---- staged epilogue: acc -> smem (padded), then coalesced stores
    __half* sh = (__half*)sm;
    __half* sl = (__half*)(sm + 34816);
    #pragma unroll
    for (int t = 0; t < 4; ++t)
        #pragma unroll
        for (int u = 0; u < 4; ++u) {
            int jl = wn * 32 + u * 8 + (lane & 3) * 2;
            #pragma unroll
            for (int h = 0; h < 2; ++h) {
                int ml = wm * 64 + t * 16 + (lane >> 2) + h * 8;
                float v0 = acc[t][u][h * 2], v1 = acc[t][u][h * 2 + 1];
                __half h0 = __float2half_rn(v0), h1 = __float2half_rn(v1);
                __half2 hv; hv.x = h0; hv.y = h1;
                __half2 lv;
                lv.x = __float2half_rn(v0 - __half2float(h0));
                lv.y = __float2half_rn(v1 - __half2float(h1));
                *(__half2*)&sh[ml * 136 + jl] = hv;
                *(__half2*)&sl[ml * 136 + jl] = lv;
            }
        }
    __syncthreads();

    const int k = colBase >> 8;                 // n' = k*256 + j
    const int jb = (colBase & 255);             // 0 or 128
    #pragma unroll
    for (int it = 0; it < 8; ++it) {
        int lin = it * 256 + tid;
        int m = lin >> 4;
        int jo = (lin & 15) * 8;
        uint4 vh = *(const uint4*)&sh[m * 136 + jo];
        uint4 vl = *(const uint4*)&sl[m * 136 + jo];
        size_t off = ((size_t)(rowBase + m) * 64 + k) * 256 + jb + jo;
        *(uint4*)(g_th + off) = vh;
        *(uint4*)(g_tl + off) = vl;
    }
}

// ---------------- stage 2: out = tanh(ctx_b @ tmp^T + Arow + Beta) ----------
// grid (128 s-pairs, 2 ztile, 8 b), 256 thr. CTA 128(z) x 128(n=(s_local,k)).
__global__ __launch_bounds__(256) void k_mma2(float* __restrict__ out) {
    extern __shared__ char sm[];
    __shared__ float beta_sm[128];
    const u32 smb = smem_u32(sm);
    const int tid = threadIdx.x, lane = tid & 31, wid = tid >> 5;
    const int wm = wid >> 2, wn = wid & 3;           // 2 x 4 warps; warp tile 64x32
    const int s0 = blockIdx.x * 2, zBase = blockIdx.y * 128, b = blockIdx.z;
    const int bs0 = b * 256 + s0;
    const size_t bRowBase = (size_t)bs0 * 64;        // row into [NBS*64][256]

    if (tid < 128) beta_sm[tid] = g_Beta[(size_t)bs0 * Vk + tid];

    auto load = [&](int c, int p) {
        u32 d = smb + p * 65536;
        const char* sA_h = (const char*)g_ch + (((size_t)(b * 256 + zBase)) * Cc + c * 64) * 2;
        const char* sA_l = (const char*)g_cl + (((size_t)(b * 256 + zBase)) * Cc + c * 64) * 2;
        const char* sB_h = (const char*)g_th + (bRowBase * Cc + c * 64) * 2;
        const char* sB_l = (const char*)g_tl + (bRowBase * Cc + c * 64) * 2;
        #pragma unroll
        for (int q = 0; q < 4; ++q) {
            int s = tid + q * 256;
            int r = s >> 3, co = (s & 7) * 16;
            u32 sw = SWZ(r * 128 + co);
            cpa16(d + sw,         sA_h + (size_t)r * 512 + co);
            cpa16(d + 16384 + sw, sA_l + (size_t)r * 512 + co);
            cpa16(d + 32768 + sw, sB_h + (size_t)r * 512 + co);
            cpa16(d + 49152 + sw, sB_l + (size_t)r * 512 + co);
        }
    };

    float acc[4][4][4];
    #pragma unroll
    for (int t = 0; t < 4; ++t)
        #pragma unroll
        for (int u = 0; u < 4; ++u)
            #pragma unroll
            for (int e = 0; e < 4; ++e) acc[t][u][e] = 0.f;

    load(0, 0); CP_COMMIT();

    for (int c = 0; c < 4; ++c) {
        CP_WAIT0();
        __syncthreads();
        if (c < 3) { load(c + 1, (c + 1) & 1); CP_COMMIT(); }
        u32 bufA = smb + (c & 1) * 65536;
        u32 bufB = bufA + 32768;
        #pragma unroll
        for (int ks = 0; ks < 4; ++ks) {
            u32 ah[4][4], al[4][4], bh[4][2], bl[4][2];
            int arow = wm * 64 + (lane & 15);
            int acol = ks * 32 + (lane >> 4) * 16;
            #pragma unroll
            for (int t = 0; t < 4; ++t) {
                u32 sw = SWZ((arow + t * 16) * 128 + acol);
                ldmA(bufA + sw,         ah[t][0], ah[t][1], ah[t][2], ah[t][3]);
                ldmA(bufA + 16384 + sw, al[t][0], al[t][1], al[t][2], al[t][3]);
            }
            int brow = wn * 32 + (lane & 7);
            int bcol = ks * 32 + ((lane >> 3) & 1) * 16;
            #pragma unroll
            for (int u = 0; u < 4; ++u) {
                u32 sw = SWZ((brow + u * 8) * 128 + bcol);
                ldmB(bufB + sw,         bh[u][0], bh[u][1]);
                ldmB(bufB + 16384 + sw, bl[u][0], bl[u][1]);
            }
            #pragma unroll
            for (int t = 0; t < 4; ++t)
                #pragma unroll
                for (int u = 0; u < 4; ++u) {
                    mma16816(acc[t][u], ah[t], bh[u]);
                    mma16816(acc[t][u], ah[t], bl[u]);
                    mma16816(acc[t][u], al[t], bh[u]);
                }
        }
        __syncthreads();
    }

    // ---- stage Arow slice (32 KB contiguous) into smem, coalesced
    float* so = (float*)sm;                       // [128 z][132 floats]
    float* sArow = (float*)(sm + 69632);          // [128 z][64 k]
    {
        const float4* src = (const float4*)&g_Arow[(size_t)(b * 256 + zBase) * Vk];
        float4* dst = (float4*)sArow;
        #pragma unroll
        for (int it = 0; it < 8; ++it)
            dst[it * 256 + tid] = src[it * 256 + tid];
    }
    __syncthreads();

    // ---- epilogue: finish math (tanh.approx), stage fp32 tile, coalesced stores
    #pragma unroll
    for (int t = 0; t < 4; ++t)
        #pragma unroll
        for (int u = 0; u < 4; ++u) {
            int n = wn * 32 + u * 8 + (lane & 3) * 2;
            int k0 = n & 63;
            #pragma unroll
            for (int h = 0; h < 2; ++h) {
                int zl = wm * 64 + t * 16 + (lane >> 2) + h * 8;
                float2 ar = *(const float2*)&sArow[zl * 64 + k0];
                float2 o;
                o.x = ftanh(acc[t][u][h * 2]     + ar.x + beta_sm[n]);
                o.y = ftanh(acc[t][u][h * 2 + 1] + ar.y + beta_sm[n + 1]);
                *(float2*)&so[zl * 132 + n] = o;
            }
        }
    __syncthreads();

    #pragma unroll
    for (int it = 0; it < 16; ++it) {
        int lin = it * 256 + tid;
        int k4 = (lin & 15) * 4;
        int z  = (lin >> 4) & 127;
        int s_local = lin >> 11;
        float4 v = *(const float4*)&so[z * 132 + s_local * 64 + k4];
        size_t oOff = (((size_t)(bs0 + s_local) * 256 + zBase + z) * Vk) + k4;
        *(float4*)&out[oOff] = v;
    }
}

// ---------------------------------------------------------------------------
extern "C" void kernel_launch(void* const* d_in, const int* in_sizes, int n_in,
                              void* d_out, int out_size) {
    const float* ctx       = (const float*)d_in[0];
    const float* W         = (const float*)d_in[1];
    const float* bias      = (const float*)d_in[2];
    const float* lin1_w    = (const float*)d_in[3];
    const float* lin1_b    = (const float*)d_in[4];
    const float* lin2_w    = (const float*)d_in[5];
    const float* lin2_b    = (const float*)d_in[6];
    const float* linmul_w  = (const float*)d_in[7];
    const float* linmul_b  = (const float*)d_in[8];
    const float* lindiff_w = (const float*)d_in[9];
    const float* lindiff_b = (const float*)d_in[10];
    float* out = (float*)d_out;

    static bool attr_set = false;
    if (!attr_set) {
        cudaFuncSetAttribute(k_mma1, cudaFuncAttributeMaxDynamicSharedMemorySize, 131072);
        cudaFuncSetAttribute(k_mma2, cudaFuncAttributeMaxDynamicSharedMemorySize, 131072);
        attr_set = true;
    }

    k_split_ctx<<<NBS * Cc / 256, 256>>>(ctx);
    k_prep_w<<<dim3(NN / 32, Cc / 32), dim3(32, 8)>>>(W, linmul_w);
    k_rowcol<<<NBS, 128>>>(ctx, lin1_w, lin1_b, lin2_w, lin2_b,
                           linmul_b, lindiff_w, lindiff_b, bias);
    k_mma1<<<dim3(128, 16), 256, 131072>>>();
    k_mma2<<<dim3(128, 2, 8), 256, 131072>>>(out);
}

// round 10
// speedup vs baseline: 1.2330x; 1.1569x over previous
#include <cuda_runtime.h>
#include <cuda_fp16.h>
#include <math.h>
#include <stdint.h>

using u32 = unsigned int;

constexpr int Cc = 256, Vk = 64, NBS = 2048, NN = 16384;

// Scratch (device globals; allocation-free)
__device__ __half g_ch[NBS * Cc], g_cl[NBS * Cc];                   // ctx split
__device__ __half g_Wh[(size_t)NN * Cc], g_Wl[(size_t)NN * Cc];     // W2' [n'=(k,j)][i]
__device__ __half g_th[(size_t)NBS * Vk * Cc];                      // tmp fp16 [bs][k][j] (134 MB)
__device__ float g_Arow[NBS * Vk], g_Beta[NBS * Vk];

// ---------------- helpers ----------------
__device__ __forceinline__ u32 smem_u32(const void* p) {
    u32 a;
    asm("{ .reg .u64 t; cvta.to.shared.u64 t, %1; cvt.u32.u64 %0, t; }" : "=r"(a) : "l"(p));
    return a;
}
#define SWZ(o) ((o) ^ (((o) >> 3) & 0x70))

__device__ __forceinline__ void cpa16(u32 dst, const void* src) {
    asm volatile("cp.async.cg.shared.global [%0], [%1], 16;" :: "r"(dst), "l"(src));
}
#define CP_COMMIT() asm volatile("cp.async.commit_group;")
#define CP_WAIT0()  asm volatile("cp.async.wait_group 0;")

__device__ __forceinline__ void ldmA(u32 addr, u32& a0, u32& a1, u32& a2, u32& a3) {
    asm volatile("ldmatrix.sync.aligned.m8n8.x4.shared.b16 {%0,%1,%2,%3}, [%4];"
                 : "=r"(a0), "=r"(a1), "=r"(a2), "=r"(a3) : "r"(addr));
}
__device__ __forceinline__ void ldmB(u32 addr, u32& b0, u32& b1) {
    asm volatile("ldmatrix.sync.aligned.m8n8.x2.shared.b16 {%0,%1}, [%2];"
                 : "=r"(b0), "=r"(b1) : "r"(addr));
}
__device__ __forceinline__ void mma16816(float* c, const u32* a, const u32* b) {
    asm volatile("mma.sync.aligned.m16n8k16.row.col.f32.f16.f16.f32 "
                 "{%0,%1,%2,%3}, {%4,%5,%6,%7}, {%8,%9}, {%0,%1,%2,%3};"
                 : "+f"(c[0]), "+f"(c[1]), "+f"(c[2]), "+f"(c[3])
                 : "r"(a[0]), "r"(a[1]), "r"(a[2]), "r"(a[3]), "r"(b[0]), "r"(b[1]));
}
__device__ __forceinline__ float ftanh(float x) {
    float y;
    asm("tanh.approx.f32 %0, %1;" : "=f"(y) : "f"(x));
    return y;
}

// ---------------- prep kernels ----------------
__global__ void k_split_ctx(const float* __restrict__ ctx) {
    int i = blockIdx.x * 256 + threadIdx.x;
    float x = ctx[i];
    __half h = __float2half_rn(x);
    g_ch[i] = h;
    g_cl[i] = __float2half_rn(x - __half2float(h));
}

// W2'[(k*256+j)][i] = W[i][j*64+k] + (i==j)*lmw[k*256+j], split hi/lo
__global__ void k_prep_w(const float* __restrict__ W, const float* __restrict__ lmw) {
    __shared__ float tile[32][33];
    int tx = threadIdx.x, ty = threadIdx.y;          // (32, 8)
    int n0 = blockIdx.x * 32, i0 = blockIdx.y * 32;
    #pragma unroll
    for (int q = 0; q < 4; ++q) {
        int i = i0 + ty + q * 8, n = n0 + tx;
        float v = W[(size_t)i * NN + n];
        int j = n >> 6, k = n & 63;
        if (i == j) v += lmw[k * Cc + j];
        tile[ty + q * 8][tx] = v;
    }
    __syncthreads();
    #pragma unroll
    for (int q = 0; q < 4; ++q) {
        int n = n0 + ty + q * 8, i = i0 + tx;
        float v = tile[tx][ty + q * 8];
        int j = n >> 6, k = n & 63;
        size_t np = (size_t)(k * 256 + j) * Cc + i;
        __half h = __float2half_rn(v);
        g_Wh[np] = h;
        g_Wl[np] = __float2half_rn(v - __half2float(h));
    }
}

__global__ void k_rowcol(const float* __restrict__ ctx,
                         const float* __restrict__ l1w, const float* __restrict__ l1b,
                         const float* __restrict__ l2w, const float* __restrict__ l2b,
                         const float* __restrict__ lmb,
                         const float* __restrict__ ldw, const float* __restrict__ ldb,
                         const float* __restrict__ bias) {
    __shared__ float xs[Cc];
    int r = blockIdx.x, t = threadIdx.x;
    for (int c = t; c < Cc; c += 128) xs[c] = ctx[r * Cc + c];
    __syncthreads();
    if (t < 64) {
        int k = t; float acc = 0.f;
        #pragma unroll 8
        for (int c = 0; c < Cc; ++c) acc = fmaf(xs[c], l1w[k * Cc + c] + ldw[k * Cc + c], acc);
        g_Arow[r * Vk + k] = acc + l1b[k];
    } else {
        int k = t - 64; float acc = 0.f;
        #pragma unroll 8
        for (int c = 0; c < Cc; ++c) acc = fmaf(xs[c], l2w[k * Cc + c] - ldw[k * Cc + c], acc);
        g_Beta[r * Vk + k] = acc + l2b[k] + lmb[k] + ldb[k] + bias[k];
    }
}

// ---------------- stage 1: tmp = ctx @ W2' (HMMA fp16 3-term split) ---------
// grid (128 n'-tiles, 16 m-tiles), 256 thr. CTA 128x128, BK=64, 4 chunks.
// tmp stored as SINGLE fp16 (hi) -> halves store traffic, fits L2.
__global__ __launch_bounds__(256) void k_mma1() {
    extern __shared__ char sm[];
    const u32 smb = smem_u32(sm);
    const int tid = threadIdx.x, lane = tid & 31, wid = tid >> 5;
    const int wm = wid >> 2, wn = wid & 3;           // 2 x 4 warps; warp tile 64x32
    const int rowBase = blockIdx.y * 128;
    const int colBase = blockIdx.x * 128;

    auto load = [&](int c, int p) {
        u32 d = smb + p * 65536;
        const char* sA_h = (const char*)g_ch + ((size_t)rowBase * Cc + c * 64) * 2;
        const char* sA_l = (const char*)g_cl + ((size_t)rowBase * Cc + c * 64) * 2;
        const char* sB_h = (const char*)g_Wh + ((size_t)colBase * Cc + c * 64) * 2;
        const char* sB_l = (const char*)g_Wl + ((size_t)colBase * Cc + c * 64) * 2;
        #pragma unroll
        for (int q = 0; q < 4; ++q) {
            int s = tid + q * 256;
            int r = s >> 3, co = (s & 7) * 16;
            u32 sw = SWZ(r * 128 + co);
            cpa16(d + sw,         sA_h + (size_t)r * 512 + co);
            cpa16(d + 16384 + sw, sA_l + (size_t)r * 512 + co);
            cpa16(d + 32768 + sw, sB_h + (size_t)r * 512 + co);
            cpa16(d + 49152 + sw, sB_l + (size_t)r * 512 + co);
        }
    };

    float acc[4][4][4];
    #pragma unroll
    for (int t = 0; t < 4; ++t)
        #pragma unroll
        for (int u = 0; u < 4; ++u)
            #pragma unroll
            for (int e = 0; e < 4; ++e) acc[t][u][e] = 0.f;

    load(0, 0); CP_COMMIT();

    for (int c = 0; c < 4; ++c) {
        CP_WAIT0();
        __syncthreads();
        if (c < 3) { load(c + 1, (c + 1) & 1); CP_COMMIT(); }
        u32 bufA = smb + (c & 1) * 65536;
        u32 bufB = bufA + 32768;
        #pragma unroll
        for (int ks = 0; ks < 4; ++ks) {
            u32 ah[4][4], al[4][4], bh[4][2], bl[4][2];
            int arow = wm * 64 + (lane & 15);
            int acol = ks * 32 + (lane >> 4) * 16;
            #pragma unroll
            for (int t = 0; t < 4; ++t) {
                u32 sw = SWZ((arow + t * 16) * 128 + acol);
                ldmA(bufA + sw,         ah[t][0], ah[t][1], ah[t][2], ah[t][3]);
                ldmA(bufA + 16384 + sw, al[t][0], al[t][1], al[t][2], al[t][3]);
            }
            int brow = wn * 32 + (lane & 7);
            int bcol = ks * 32 + ((lane >> 3) & 1) * 16;
            #pragma unroll
            for (int u = 0; u < 4; ++u) {
                u32 sw = SWZ((brow + u * 8) * 128 + bcol);
                ldmB(bufB + sw,         bh[u][0], bh[u][1]);
                ldmB(bufB + 16384 + sw, bl[u][0], bl[u][1]);
            }
            #pragma unroll
            for (int t = 0; t < 4; ++t)
                #pragma unroll
                for (int u = 0; u < 4; ++u) {
                    mma16816(acc[t][u], ah[t], bh[u]);
                    mma16816(acc[t][u], ah[t], bl[u]);
                    mma16816(acc[t][u], al[t], bh[u]);
                }
        }
        __syncthreads();
    }

    // ---- staged epilogue: hi-only fp16 -> smem (padded), coalesced stores
    __half* sh = (__half*)sm;                    // [128][136] = 34816 B (buf0; safe)
    #pragma unroll
    for (int t = 0; t < 4; ++t)
        #pragma unroll
        for (int u = 0; u < 4; ++u) {
            int jl = wn * 32 + u * 8 + (lane & 3) * 2;
            #pragma unroll
            for (int h = 0; h < 2; ++h) {
                int ml = wm * 64 + t * 16 + (lane >> 2) + h * 8;
                __half2 hv;
                hv.x = __float2half_rn(acc[t][u][h * 2]);
                hv.y = __float2half_rn(acc[t][u][h * 2 + 1]);
                *(__half2*)&sh[ml * 136 + jl] = hv;
            }
        }
    __syncthreads();

    const int k = colBase >> 8;                 // n' = k*256 + j
    const int jb = (colBase & 255);             // 0 or 128
    #pragma unroll
    for (int it = 0; it < 8; ++it) {
        int lin = it * 256 + tid;
        int m = lin >> 4;
        int jo = (lin & 15) * 8;
        uint4 vh = *(const uint4*)&sh[m * 136 + jo];
        size_t off = ((size_t)(rowBase + m) * 64 + k) * 256 + jb + jo;
        *(uint4*)(g_th + off) = vh;
    }
}

// ---------------- stage 2: out = tanh(ctx_b @ tmp^T + Arow + Beta) ----------
// grid (128 s-pairs, 2 ztile, 8 b), 256 thr, 2 CTAs/SM.
// SINGLE-TERM fp16: A = ctx hi, B = tmp fp16. 16 MMAs per ks (was 48).
// smem: 2 bufs x (Ah 16K | Bh 16K) = 64 KB; epilogue reuses as fp32 stage.
__global__ __launch_bounds__(256, 2) void k_mma2(float* __restrict__ out) {
    extern __shared__ char sm[];
    __shared__ float beta_sm[128];
    const u32 smb = smem_u32(sm);
    const int tid = threadIdx.x, lane = tid & 31, wid = tid >> 5;
    const int wm = wid >> 2, wn = wid & 3;           // 2 x 4 warps; warp tile 64x32
    const int s0 = blockIdx.x * 2, zBase = blockIdx.y * 128, b = blockIdx.z;
    const int bs0 = b * 256 + s0;
    const size_t bRowBase = (size_t)bs0 * 64;        // row into [NBS*64][256]

    if (tid < 128) beta_sm[tid] = g_Beta[(size_t)bs0 * Vk + tid];

    auto load = [&](int c, int p) {
        u32 d = smb + p * 32768;
        const char* sA = (const char*)g_ch + (((size_t)(b * 256 + zBase)) * Cc + c * 64) * 2;
        const char* sB = (const char*)g_th + (bRowBase * Cc + c * 64) * 2;
        #pragma unroll
        for (int q = 0; q < 4; ++q) {
            int s = tid + q * 256;
            int r = s >> 3, co = (s & 7) * 16;
            u32 sw = SWZ(r * 128 + co);
            cpa16(d + sw,         sA + (size_t)r * 512 + co);
            cpa16(d + 16384 + sw, sB + (size_t)r * 512 + co);
        }
    };

    float acc[4][4][4];
    #pragma unroll
    for (int t = 0; t < 4; ++t)
        #pragma unroll
        for (int u = 0; u < 4; ++u)
            #pragma unroll
            for (int e = 0; e < 4; ++e) acc[t][u][e] = 0.f;

    load(0, 0); CP_COMMIT();

    for (int c = 0; c < 4; ++c) {
        CP_WAIT0();
        __syncthreads();
        if (c < 3) { load(c + 1, (c + 1) & 1); CP_COMMIT(); }
        u32 bufA = smb + (c & 1) * 32768;
        u32 bufB = bufA + 16384;
        #pragma unroll
        for (int ks = 0; ks < 4; ++ks) {
            u32 ah[4][4], bh[4][2];
            int arow = wm * 64 + (lane & 15);
            int acol = ks * 32 + (lane >> 4) * 16;
            #pragma unroll
            for (int t = 0; t < 4; ++t) {
                u32 sw = SWZ((arow + t * 16) * 128 + acol);
                ldmA(bufA + sw, ah[t][0], ah[t][1], ah[t][2], ah[t][3]);
            }
            int brow = wn * 32 + (lane & 7);
            int bcol = ks * 32 + ((lane >> 3) & 1) * 16;
            #pragma unroll
            for (int u = 0; u < 4; ++u) {
                u32 sw = SWZ((brow + u * 8) * 128 + bcol);
                ldmB(bufB + sw, bh[u][0], bh[u][1]);
            }
            #pragma unroll
            for (int t = 0; t < 4; ++t)
                #pragma unroll
                for (int u = 0; u < 4; ++u)
                    mma16816(acc[t][u], ah[t], bh[u]);
        }
        __syncthreads();
    }

    // ---- epilogue: finish math, stage fp32 tile in smem, coalesced stores
    float* so = (float*)sm;                       // [128 z][132 floats] = 67584 B
    #pragma unroll
    for (int t = 0; t < 4; ++t)
        #pragma unroll
        for (int u = 0; u < 4; ++u) {
            int n = wn * 32 + u * 8 + (lane & 3) * 2;
            int k0 = n & 63;
            #pragma unroll
            for (int h = 0; h < 2; ++h) {
                int zl = wm * 64 + t * 16 + (lane >> 2) + h * 8;
                float2 ar = *(const float2*)&g_Arow[(size_t)(b * 256 + zBase + zl) * Vk + k0];
                float2 o;
                o.x = ftanh(acc[t][u][h * 2]     + ar.x + beta_sm[n]);
                o.y = ftanh(acc[t][u][h * 2 + 1] + ar.y + beta_sm[n + 1]);
                *(float2*)&so[zl * 132 + n] = o;
            }
        }
    __syncthreads();

    #pragma unroll
    for (int it = 0; it < 16; ++it) {
        int lin = it * 256 + tid;
        int k4 = (lin & 15) * 4;
        int z  = (lin >> 4) & 127;
        int s_local = lin >> 11;
        float4 v = *(const float4*)&so[z * 132 + s_local * 64 + k4];
        size_t oOff = (((size_t)(bs0 + s_local) * 256 + zBase + z) * Vk) + k4;
        *(float4*)&out[oOff] = v;
    }
}

// ---------------------------------------------------------------------------
extern "C" void kernel_launch(void* const* d_in, const int* in_sizes, int n_in,
                              void* d_out, int out_size) {
    const float* ctx       = (const float*)d_in[0];
    const float* W         = (const float*)d_in[1];
    const float* bias      = (const float*)d_in[2];
    const float* lin1_w    = (const float*)d_in[3];
    const float* lin1_b    = (const float*)d_in[4];
    const float* lin2_w    = (const float*)d_in[5];
    const float* lin2_b    = (const float*)d_in[6];
    const float* linmul_w  = (const float*)d_in[7];
    const float* linmul_b  = (const float*)d_in[8];
    const float* lindiff_w = (const float*)d_in[9];
    const float* lindiff_b = (const float*)d_in[10];
    float* out = (float*)d_out;

    static bool attr_set = false;
    if (!attr_set) {
        cudaFuncSetAttribute(k_mma1, cudaFuncAttributeMaxDynamicSharedMemorySize, 131072);
        cudaFuncSetAttribute(k_mma2, cudaFuncAttributeMaxDynamicSharedMemorySize, 69632);
        attr_set = true;
    }

    k_split_ctx<<<NBS * Cc / 256, 256>>>(ctx);
    k_prep_w<<<dim3(NN / 32, Cc / 32), dim3(32, 8)>>>(W, linmul_w);
    k_rowcol<<<NBS, 128>>>(ctx, lin1_w, lin1_b, lin2_w, lin2_b,
                           linmul_b, lindiff_w, lindiff_b, bias);
    k_mma1<<<dim3(128, 16), 256, 131072>>>();
    k_mma2<<<dim3(128, 2, 8), 256, 69632>>>(out);
}